// round 15
// baseline (speedup 1.0000x reference)
#include <cuda_runtime.h>
#include <cuda_fp16.h>
#include <math.h>

// Problem constants
#define R_    2048
#define C_    1024
#define NCH   8

#define RPB   16                 // rows per block (phase 1)
#define NB    (R_ / RPB)         // 128 blocks
#define NT    512                // threads per block

// Scratch (no allocations allowed -> device globals)
__device__ __half g_LpH[NB * NCH * C_];    // per-block partial L, fp16 (2MB)
__device__ float g_pA[64 * NB];            // [i][blk] partial sum_r P*s
__device__ float g_pB[64 * NB];            // [i][blk] partial sum_r P
__device__ float g_pSel[NB];               // per-block row-sel partials
__device__ float g_nnz[64];                // reduced nnz_ch_ba
__device__ float g_psum[64];               // reduced sum_r P
__device__ float g_ncolPart[NB];           // per-block colch sums
__device__ float g_selv;                   // reduced row-sel count
__device__ unsigned int g_done;            // barrier arrivals (reset at end)
__device__ unsigned int g_count;           // finalize ticket (reset at end)

// ---------------------------------------------------------------------------
// Single kernel, 128 blocks x 512 threads.
// Phase 1: softmax 1 row/warp; stream D tile once (float2/thread); write
//          fp16 Lpart + pA/pB/sel partials.
// Barrier: one atomicAdd arrival per block; warp 0 polls with backoff.
// Phase 2: block b reduces its 64 outputs over 128 fp16 partials with TWO
//          uint4 loads/thread; colch = 1-exp; spare warps reduce pA/pB/sel.
// Ticket:  last block writes the 105 scalars, resets counters.
// Output layout: P[131072] | tot[8] | max_nnz[8] | num_col[8] | num_row[8] |
//                nnz_ch_ba[64] | col_density[8] | num_row_sel[1]
// ---------------------------------------------------------------------------
__global__ __launch_bounds__(NT) void k_all(const float* __restrict__ W,
                                            const float* __restrict__ D,
                                            const float* __restrict__ G,
                                            float* __restrict__ out)
{
    __shared__ float sP[RPB][64];
    __shared__ float slq[RPB][NCH];
    __shared__ float sds[RPB][16];
    __shared__ float sSel[RPB];
    __shared__ float sS[RPB];
    __shared__ float sred[64][64];         // phase-2 staging (16KB)

    const int t    = threadIdx.x;
    const int wid  = t >> 5;               // 0..15
    const int lane = t & 31;
    const int b    = blockIdx.x;
    const int r0   = b * RPB;

    const float2* W2 = reinterpret_cast<const float2*>(W);
    const float2* G2 = reinterpret_cast<const float2*>(G);

    // ================= Phase 1 =================
    // ---- softmax: one row per warp ----
    {
        const int rl = wid;
        const int r  = r0 + rl;

        float2 w  = W2[r * 32 + lane];
        float2 gv = G2[r * 32 + lane];
        float e0 = w.x + gv.x;
        float e1 = w.y + gv.y;

        float m = fmaxf(e0, e1);
        #pragma unroll
        for (int o = 16; o > 0; o >>= 1)
            m = fmaxf(m, __shfl_xor_sync(0xFFFFFFFFu, m, o));

        float x0 = expf(e0 - m);
        float x1 = expf(e1 - m);
        float s  = x0 + x1;
        #pragma unroll
        for (int o = 16; o > 0; o >>= 1)
            s += __shfl_xor_sync(0xFFFFFFFFu, s, o);

        const float inv = 1.0f / s;        // == max(P): exp(0)=1 at the argmax
        const float p0  = x0 * inv;
        const float p1  = x1 * inv;

        reinterpret_cast<float2*>(out)[r * 32 + lane] = make_float2(p0, p1);
        sP[rl][2 * lane]     = p0;
        sP[rl][2 * lane + 1] = p1;

        float lq = log1pf(-p0) + log1pf(-p1);
        lq += __shfl_xor_sync(0xFFFFFFFFu, lq, 1);
        lq += __shfl_xor_sync(0xFFFFFFFFu, lq, 2);
        if ((lane & 3) == 0) slq[rl][lane >> 2] = lq;
        if (lane == 0) sSel[rl] = (inv > 0.99f) ? 1.0f : 0.0f;
    }
    __syncthreads();

    // ---- stream D tile once; 2 cols per thread (float2) ----
    {
        float accx[NCH], accy[NCH];
        #pragma unroll
        for (int ch = 0; ch < NCH; ch++) { accx[ch] = 0.f; accy[ch] = 0.f; }
        float dsv[RPB];

        const float2* D2 = reinterpret_cast<const float2*>(D);
        #pragma unroll
        for (int rl = 0; rl < RPB; rl++) {
            float2 d = D2[(size_t)(r0 + rl) * 512 + t];
            dsv[rl] = d.x + d.y;
            #pragma unroll
            for (int ch = 0; ch < NCH; ch++) {
                float l = slq[rl][ch];
                accx[ch] = fmaf(d.x, l, accx[ch]);
                accy[ch] = fmaf(d.y, l, accy[ch]);
            }
        }
        #pragma unroll
        for (int rl = 0; rl < RPB; rl++) {
            float v = dsv[rl];
            #pragma unroll
            for (int o = 16; o > 0; o >>= 1)
                v += __shfl_xor_sync(0xFFFFFFFFu, v, o);
            if (lane == 0) sds[rl][wid] = v;
        }

        // fp16 Lpart: half2 per (ch, col-pair), coalesced
        __half2* LpH2 = reinterpret_cast<__half2*>(g_LpH);
        #pragma unroll
        for (int ch = 0; ch < NCH; ch++)
            LpH2[b * 4096 + ch * 512 + t] = __floats2half2_rn(accx[ch], accy[ch]);
    }
    __syncthreads();

    if (t < RPB) {
        float v = 0.f;
        #pragma unroll
        for (int w2 = 0; w2 < 16; w2++) v += sds[t][w2];
        sS[t] = v;
    }
    __syncthreads();

    if (t < 64) {
        float a = 0.f, bb = 0.f;
        #pragma unroll
        for (int rl = 0; rl < RPB; rl++) {
            float p = sP[rl][t];
            bb += p;
            a   = fmaf(p, sS[rl], a);
        }
        g_pA[t * NB + b] = a;
        g_pB[t * NB + b] = bb;
    }
    if (t == 0) {
        float v = 0.f;
        #pragma unroll
        for (int rl = 0; rl < RPB; rl++) v += sSel[rl];
        g_pSel[b] = v;
    }

    // ================= Barrier =================
    __syncthreads();
    if (t == 0) { __threadfence(); atomicAdd(&g_done, 1u); }
    if (t < 32) {
        while (*(volatile unsigned int*)&g_done < NB) __nanosleep(32);
    }
    __syncthreads();
    if (t == 0) __threadfence();           // single L1-flush / acquire
    __syncthreads();

    // ================= Phase 2 (fp16, 2 loads/thread) =================
    {
        // block b owns outputs o in [b*64, b*64+64) (one channel).
        // thread (q = t&7 -> 8 outputs, pg = t>>3 -> 2 partials): 2 uint4 loads.
        const int q  = t & 7;
        const int pg = t >> 3;             // 0..63
        const uint4* Lp = reinterpret_cast<const uint4*>(g_LpH);
        const int base = b * 8 + q;        // uint4 index within a partial row
        uint4 u0 = Lp[(size_t)(pg * 2 + 0) * 1024 + base];
        uint4 u1 = Lp[(size_t)(pg * 2 + 1) * 1024 + base];

        float2 f0 = __half22float2(*reinterpret_cast<__half2*>(&u0.x));
        float2 f1 = __half22float2(*reinterpret_cast<__half2*>(&u0.y));
        float2 f2 = __half22float2(*reinterpret_cast<__half2*>(&u0.z));
        float2 f3 = __half22float2(*reinterpret_cast<__half2*>(&u0.w));
        float2 g0 = __half22float2(*reinterpret_cast<__half2*>(&u1.x));
        float2 g1 = __half22float2(*reinterpret_cast<__half2*>(&u1.y));
        float2 g2 = __half22float2(*reinterpret_cast<__half2*>(&u1.z));
        float2 g3 = __half22float2(*reinterpret_cast<__half2*>(&u1.w));

        float4 a = make_float4(f0.x + g0.x, f0.y + g0.y, f1.x + g1.x, f1.y + g1.y);
        float4 c = make_float4(f2.x + g2.x, f2.y + g2.y, f3.x + g3.x, f3.y + g3.y);
        *reinterpret_cast<float4*>(&sred[pg][q * 8])     = a;
        *reinterpret_cast<float4*>(&sred[pg][q * 8 + 4]) = c;
        __syncthreads();

        __shared__ float cs[2];
        if (t < 64) {
            float L = 0.f;
            #pragma unroll
            for (int k = 0; k < 64; k++) L += sred[k][t];
            float colch = 1.0f - expf(L);
            #pragma unroll
            for (int o = 16; o > 0; o >>= 1)
                colch += __shfl_xor_sync(0xFFFFFFFFu, colch, o);
            if (lane == 0) cs[t >> 5] = colch;
        }

        // spare warps: reduce pA / pB / sel (coalesced rows of 128)
        if (wid == 8 && b < 64) {
            float v = g_pA[b * NB + lane]      + g_pA[b * NB + lane + 32]
                    + g_pA[b * NB + lane + 64] + g_pA[b * NB + lane + 96];
            #pragma unroll
            for (int o = 16; o > 0; o >>= 1)
                v += __shfl_xor_sync(0xFFFFFFFFu, v, o);
            if (lane == 0) g_nnz[b] = v;
        } else if (wid == 9 && b < 64) {
            float v = g_pB[b * NB + lane]      + g_pB[b * NB + lane + 32]
                    + g_pB[b * NB + lane + 64] + g_pB[b * NB + lane + 96];
            #pragma unroll
            for (int o = 16; o > 0; o >>= 1)
                v += __shfl_xor_sync(0xFFFFFFFFu, v, o);
            if (lane == 0) g_psum[b] = v;
        } else if (wid == 10 && b == 64) {
            float v = g_pSel[lane]      + g_pSel[lane + 32]
                    + g_pSel[lane + 64] + g_pSel[lane + 96];
            #pragma unroll
            for (int o = 16; o > 0; o >>= 1)
                v += __shfl_xor_sync(0xFFFFFFFFu, v, o);
            if (lane == 0) g_selv = v;
        }
        __syncthreads();
        if (t == 0) g_ncolPart[b] = cs[0] + cs[1];
    }

    // ================= Ticket finalize =================
    __shared__ int isLast;
    __syncthreads();
    if (t == 0) {
        __threadfence();
        unsigned int old = atomicAdd(&g_count, 1u);
        isLast = (old == NB - 1) ? 1 : 0;
        if (isLast) { g_count = 0; g_done = 0; }   // reset for next replay
    }
    __syncthreads();
    if (!isLast) return;
    if (t == 0) __threadfence();           // single acquire / L1 flush
    __syncthreads();

    if (t < 64) out[131104 + t] = g_nnz[t];         // nnz_ch_ba

    if (t < NCH) {
        float m = -1e30f, ns = 0.f, rs = 0.f;
        #pragma unroll
        for (int ba = 0; ba < 8; ba++) {
            float nv = g_nnz[t * 8 + ba];
            m  = fmaxf(m, nv);
            ns += nv;
            rs += g_psum[t * 8 + ba];
        }
        float ncl = 0.f;
        #pragma unroll
        for (int k = 0; k < 16; k++) ncl += g_ncolPart[t * 16 + k];
        out[131072 + t] = m + ncl + rs;             // tot_ch
        out[131080 + t] = m;                        // max_nnz_ch
        out[131088 + t] = ncl;                      // num_col_ch
        out[131096 + t] = rs;                       // num_row_ch
        out[131168 + t] = ns / rs / ncl;            // col_density_ch
    }
    if (t == 64) out[131176] = g_selv;              // num_row_sel
}

// ---------------------------------------------------------------------------
extern "C" void kernel_launch(void* const* d_in, const int* in_sizes, int n_in,
                              void* d_out, int out_size)
{
    const float* W = (const float*)d_in[0];   // [2048, 64]
    const float* D = (const float*)d_in[1];   // [2048, 1024]
    const float* G = (const float*)d_in[2];   // [2048, 64]
    // d_in[3] = i, unused by the math
    float* out = (float*)d_out;

    k_all<<<NB, NT>>>(W, D, G, out);
}

// round 16
// speedup vs baseline: 1.0200x; 1.0200x over previous
#include <cuda_runtime.h>
#include <cuda_fp16.h>
#include <math.h>

// Problem constants
#define R_    2048
#define C_    1024
#define NCH   8

#define RPB   16                 // rows per block
#define NB    (R_ / RPB)         // 128 blocks
#define NT    512                // threads per block
#define NREP  4                  // L replicas (atomic contention spreading)

// Scratch (no allocations allowed -> device globals; zero-init at load)
__device__ __half2 g_Lh[NREP][NCH * 512];  // atomically accumulated L (4x16KB)
__device__ float g_pA[64 * NB];            // [i][blk] partial sum_r P*s
__device__ float g_pB[64 * NB];            // [i][blk] partial sum_r P
__device__ float g_pSel[NB];               // per-block row-sel partials
__device__ unsigned int g_count;           // ticket (finalizer resets)

// ---------------------------------------------------------------------------
// Single kernel, 128 blocks x 512 threads — NO grid barrier.
// Each block: softmax (1 row/warp, 16 rows) -> P, lq in smem; stream its
// 16x1024 D tile once (float2/thread, 16 accs) + row sums; fire-and-forget
// RED.F16x2 of its L partials into g_Lh[b&3]; write pA/pB/sel; take ticket;
// exit. Last block: read g_Lh (32KB), colch = 1-exp (deterministically 1.0f
// per column since L ~ -25), per-channel sums; reduce pA/pB/sel; write the
// 105 scalars; re-zero g_Lh + ticket for graph replay.
// Output layout: P[131072] | tot[8] | max_nnz[8] | num_col[8] | num_row[8] |
//                nnz_ch_ba[64] | col_density[8] | num_row_sel[1]
// ---------------------------------------------------------------------------
__global__ __launch_bounds__(NT) void k_all(const float* __restrict__ W,
                                            const float* __restrict__ D,
                                            const float* __restrict__ G,
                                            float* __restrict__ out)
{
    __shared__ float sP[RPB][64];
    __shared__ float slq[RPB][NCH];
    __shared__ float sds[RPB][16];
    __shared__ float sSel[RPB];
    __shared__ float sS[RPB];

    const int t    = threadIdx.x;
    const int wid  = t >> 5;               // 0..15
    const int lane = t & 31;
    const int b    = blockIdx.x;
    const int r0   = b * RPB;

    const float2* W2 = reinterpret_cast<const float2*>(W);
    const float2* G2 = reinterpret_cast<const float2*>(G);

    // ---- softmax: one row per warp ----
    {
        const int rl = wid;
        const int r  = r0 + rl;

        float2 w  = W2[r * 32 + lane];
        float2 gv = G2[r * 32 + lane];
        float e0 = w.x + gv.x;
        float e1 = w.y + gv.y;

        float m = fmaxf(e0, e1);
        #pragma unroll
        for (int o = 16; o > 0; o >>= 1)
            m = fmaxf(m, __shfl_xor_sync(0xFFFFFFFFu, m, o));

        float x0 = expf(e0 - m);
        float x1 = expf(e1 - m);
        float s  = x0 + x1;
        #pragma unroll
        for (int o = 16; o > 0; o >>= 1)
            s += __shfl_xor_sync(0xFFFFFFFFu, s, o);

        const float inv = 1.0f / s;        // == max(P): exp(0)=1 at the argmax
        const float p0  = x0 * inv;
        const float p1  = x1 * inv;

        reinterpret_cast<float2*>(out)[r * 32 + lane] = make_float2(p0, p1);
        sP[rl][2 * lane]     = p0;
        sP[rl][2 * lane + 1] = p1;

        float lq = log1pf(-p0) + log1pf(-p1);
        lq += __shfl_xor_sync(0xFFFFFFFFu, lq, 1);
        lq += __shfl_xor_sync(0xFFFFFFFFu, lq, 2);
        if ((lane & 3) == 0) slq[rl][lane >> 2] = lq;
        if (lane == 0) sSel[rl] = (inv > 0.99f) ? 1.0f : 0.0f;
    }
    __syncthreads();

    // ---- stream D tile once; 2 cols per thread (float2) ----
    {
        float accx[NCH], accy[NCH];
        #pragma unroll
        for (int ch = 0; ch < NCH; ch++) { accx[ch] = 0.f; accy[ch] = 0.f; }
        float dsv[RPB];

        const float2* D2 = reinterpret_cast<const float2*>(D);
        #pragma unroll
        for (int rl = 0; rl < RPB; rl++) {
            float2 d = D2[(size_t)(r0 + rl) * 512 + t];
            dsv[rl] = d.x + d.y;
            #pragma unroll
            for (int ch = 0; ch < NCH; ch++) {
                float l = slq[rl][ch];
                accx[ch] = fmaf(d.x, l, accx[ch]);
                accy[ch] = fmaf(d.y, l, accy[ch]);
            }
        }
        #pragma unroll
        for (int rl = 0; rl < RPB; rl++) {
            float v = dsv[rl];
            #pragma unroll
            for (int o = 16; o > 0; o >>= 1)
                v += __shfl_xor_sync(0xFFFFFFFFu, v, o);
            if (lane == 0) sds[rl][wid] = v;
        }

        // fire-and-forget: RED.F16x2 the L partials (thread t = col pair t)
        __half2* Lrep = g_Lh[b & (NREP - 1)];
        #pragma unroll
        for (int ch = 0; ch < NCH; ch++)
            atomicAdd(&Lrep[ch * 512 + t], __floats2half2_rn(accx[ch], accy[ch]));
    }
    __syncthreads();

    if (t < RPB) {
        float v = 0.f;
        #pragma unroll
        for (int w2 = 0; w2 < 16; w2++) v += sds[t][w2];
        sS[t] = v;
    }
    __syncthreads();

    if (t < 64) {
        float a = 0.f, bb = 0.f;
        #pragma unroll
        for (int rl = 0; rl < RPB; rl++) {
            float p = sP[rl][t];
            bb += p;
            a   = fmaf(p, sS[rl], a);
        }
        g_pA[t * NB + b] = a;
        g_pB[t * NB + b] = bb;
    }
    if (t == 0) {
        float v = 0.f;
        #pragma unroll
        for (int rl = 0; rl < RPB; rl++) v += sSel[rl];
        g_pSel[b] = v;
    }

    // ---- ticket: everyone but the last block exits ----
    __shared__ int isLast;
    __syncthreads();
    if (t == 0) {
        __threadfence();                       // order REDs/pA/pB/sel first
        unsigned int old = atomicAdd(&g_count, 1u);
        isLast = (old == NB - 1) ? 1 : 0;
        if (isLast) g_count = 0;               // reset for next replay
    }
    __syncthreads();
    if (!isLast) return;
    __threadfence();                            // acquire all blocks' writes
    __syncthreads();

    // ================= Finalize (last block only, 512 threads) =================
    __shared__ float swc[16][NCH];              // per-warp per-ch colch sums
    __shared__ float snn[64], sps[64];
    __shared__ float ssel;

    // colch: thread t handles col-pair t for all 8 channels
    {
        float csum[NCH];
        #pragma unroll
        for (int ch = 0; ch < NCH; ch++) {
            __half2 h = g_Lh[0][ch * 512 + t];
            __half2 h1 = g_Lh[1][ch * 512 + t];
            __half2 h2 = g_Lh[2][ch * 512 + t];
            __half2 h3 = g_Lh[3][ch * 512 + t];
            float2 f0 = __half22float2(h);
            float2 f1 = __half22float2(h1);
            float2 f2 = __half22float2(h2);
            float2 f3 = __half22float2(h3);
            float Lx = (f0.x + f1.x) + (f2.x + f3.x);
            float Ly = (f0.y + f1.y) + (f2.y + f3.y);
            csum[ch] = (1.0f - expf(Lx)) + (1.0f - expf(Ly));
            // re-zero for next graph replay
            g_Lh[0][ch * 512 + t] = __half2(__float2half(0.f), __float2half(0.f));
            g_Lh[1][ch * 512 + t] = __half2(__float2half(0.f), __float2half(0.f));
            g_Lh[2][ch * 512 + t] = __half2(__float2half(0.f), __float2half(0.f));
            g_Lh[3][ch * 512 + t] = __half2(__float2half(0.f), __float2half(0.f));
        }
        #pragma unroll
        for (int ch = 0; ch < NCH; ch++) {
            float v = csum[ch];
            #pragma unroll
            for (int o = 16; o > 0; o >>= 1)
                v += __shfl_xor_sync(0xFFFFFFFFu, v, o);
            if (lane == 0) swc[wid][ch] = v;
        }
    }

    // nnz / psum: warp wid reduces outputs i = wid*4 .. wid*4+3
    #pragma unroll
    for (int k = 0; k < 4; k++) {
        const int i = wid * 4 + k;
        float va = g_pA[i * NB + lane]      + g_pA[i * NB + lane + 32]
                 + g_pA[i * NB + lane + 64] + g_pA[i * NB + lane + 96];
        float vb = g_pB[i * NB + lane]      + g_pB[i * NB + lane + 32]
                 + g_pB[i * NB + lane + 64] + g_pB[i * NB + lane + 96];
        #pragma unroll
        for (int o = 16; o > 0; o >>= 1) {
            va += __shfl_xor_sync(0xFFFFFFFFu, va, o);
            vb += __shfl_xor_sync(0xFFFFFFFFu, vb, o);
        }
        if (lane == 0) { snn[i] = va; sps[i] = vb; }
    }
    if (wid == 0) {                             // sel over 128 partials
        float v = g_pSel[lane]      + g_pSel[lane + 32]
                + g_pSel[lane + 64] + g_pSel[lane + 96];
        #pragma unroll
        for (int o = 16; o > 0; o >>= 1)
            v += __shfl_xor_sync(0xFFFFFFFFu, v, o);
        if (lane == 0) ssel = v;
    }
    __syncthreads();

    if (t < 64) out[131104 + t] = snn[t];       // nnz_ch_ba

    if (t < NCH) {
        float m = -1e30f, ns = 0.f, rs = 0.f;
        #pragma unroll
        for (int ba = 0; ba < 8; ba++) {
            float nv = snn[t * 8 + ba];
            m  = fmaxf(m, nv);
            ns += nv;
            rs += sps[t * 8 + ba];
        }
        float ncl = 0.f;
        #pragma unroll
        for (int w2 = 0; w2 < 16; w2++) ncl += swc[w2][t];
        out[131072 + t] = m + ncl + rs;         // tot_ch
        out[131080 + t] = m;                    // max_nnz_ch
        out[131088 + t] = ncl;                  // num_col_ch
        out[131096 + t] = rs;                   // num_row_ch
        out[131168 + t] = ns / rs / ncl;        // col_density_ch
    }
    if (t == 64) out[131176] = ssel;            // num_row_sel
}

// ---------------------------------------------------------------------------
extern "C" void kernel_launch(void* const* d_in, const int* in_sizes, int n_in,
                              void* d_out, int out_size)
{
    const float* W = (const float*)d_in[0];   // [2048, 64]
    const float* D = (const float*)d_in[1];   // [2048, 1024]
    const float* G = (const float*)d_in[2];   // [2048, 64]
    // d_in[3] = i, unused by the math
    float* out = (float*)d_out;

    k_all<<<NB, NT>>>(W, D, G, out);
}